// round 15
// baseline (speedup 1.0000x reference)
#include <cuda_runtime.h>
#include <math.h>

// VectorQuantizer: N=65536 (64x32x32 BHWC-flat), C=64, K=1024.
// Output (float32): [quantized 4194304][vq_loss 1][indices 65536][perplexity 1]
// Numerics verified bit-exact R1/R5/R7/R9/R10/R12/R13/R14.
// R15 = R14 mainloop (92% of ffma2-rt3 roofline) with cheaper plumbing:
//  - split winners via plain-store partials g_part (no g_win init, no atomicMin)
//  - replay-invariant mod-tickets (g_cnt/g_done never initialized)
//  - vq_pre shrunk to 1024 threads (esq + hist + loss only)

#define NPTS   65536
#define KC     1024
#define CD     64
#define HW     1024
#define MT     128
#define KCH    64
#define NSPLIT 4
#define CHPS   4              // chunks per split (4*64 = 256 codes)
#define NTILE  (NPTS / MT)    // 512
#define XSTRIDE 132
#define ESTRIDE 68
#define ESBUF   (KCH * ESTRIDE)

#define SM_XS   0
#define SM_ES0  (CD * XSTRIDE)           // 8448
#define SM_AS   (SM_ES0 + 2 * ESBUF)     // 17152
#define SM_IDX  (SM_AS + 128)
#define SMEM_FLOATS (SM_IDX + 128)       // 69,632 B -> 2 blocks/SM
#define SMEM_BYTES  (SMEM_FLOATS * 4)

#define OFF_LOSS  4194304
#define OFF_IDX   4194305
#define OFF_PERP  4259841

typedef unsigned long long u64;
typedef unsigned int u32;

__device__ float        g_esq[KC];
__device__ unsigned int g_hist[KC];
__device__ double       g_loss;
__device__ u64          g_part[NTILE * NSPLIT * MT];  // per-split packed winners
__device__ int          g_cnt[NTILE];    // mod-NSPLIT tickets (never re-init)
__device__ int          g_done;          // mod-NTILE ticket (never re-init)

__device__ __forceinline__ u64 pack_dup(float x) {
    u64 r; asm("mov.b64 %0, {%1, %1};" : "=l"(r) : "f"(x)); return r;
}
__device__ __forceinline__ void unpack2(u64 v, float &lo, float &hi) {
    asm("mov.b64 {%0, %1}, %2;" : "=f"(lo), "=f"(hi) : "l"(v));
}
// packed fp32x2 FMA: each lane is IEEE-rn fp32 FMA (bit-identical to scalar FFMA)
__device__ __forceinline__ void ffma2(u64 &acc, u64 a, u64 b) {
    asm("fma.rn.f32x2 %0, %1, %2, %0;" : "+l"(acc) : "l"(a), "l"(b));
}
__device__ __forceinline__ u64 ffma2_3(u64 a, u64 b, u64 c) {
    u64 r; asm("fma.rn.f32x2 %0, %1, %2, %3;" : "=l"(r) : "l"(a), "l"(b), "l"(c)); return r;
}
__device__ __forceinline__ u64 fadd2(u64 a, u64 b) {
    u64 r; asm("add.rn.f32x2 %0, %1, %2;" : "=l"(r) : "l"(a), "l"(b)); return r;
}
__device__ __forceinline__ u64 umin64(u64 a, u64 b) { return a < b ? a : b; }
__device__ __forceinline__ u32 smem_u32(const void* p) {
    u32 a; asm("{ .reg .u64 t; cvta.to.shared.u64 t, %1; cvt.u32.u64 %0, t; }" : "=r"(a) : "l"(p));
    return a;
}
__device__ __forceinline__ void cp16(u32 dst, const void* src) {
    asm volatile("cp.async.cg.shared.global [%0], [%1], 16;" :: "r"(dst), "l"(src));
}
__device__ __forceinline__ void cp_commit() {
    asm volatile("cp.async.commit_group;" ::: "memory");
}
__device__ __forceinline__ void cp_wait0() {
    asm volatile("cp.async.wait_group 0;" ::: "memory");
}

// ---------------- pre: esq + hist/loss init (1024 threads) ----------------
__global__ void vq_pre(const float* __restrict__ emb) {
    int tid = blockIdx.x * blockDim.x + threadIdx.x;   // 0..1023
    float s = 0.0f;
    const float* er = emb + (size_t)tid * CD;
    #pragma unroll
    for (int c = 0; c < CD; ++c) {
        float e = er[c];
        s = __fadd_rn(s, __fmul_rn(e, e));
    }
    g_esq[tid] = s;
    g_hist[tid] = 0u;
    if (tid == 0) g_loss = 0.0;
}

// ------- job = (tile, ksplit): distances + argmin partials; last split per
//         tile finalizes; globally-last finisher emits loss + perplexity -------
__global__ void __launch_bounds__(256, 2) vq_main(const float* __restrict__ inputs,
                                                  const float* __restrict__ emb,
                                                  float* __restrict__ out) {
    extern __shared__ float sm[];
    float* xs   = sm + SM_XS;    // [CD][XSTRIDE]  xs[c*XSTRIDE + p]
    float* as_  = sm + SM_AS;    // [128] ||x||^2 (point-pair aligned)
    int*   idxs = (int*)(sm + SM_IDX);
    double* red = (double*)(sm + SM_ES0);  // tail scratch (es dead then)
    __shared__ int lastFlag;
    __shared__ int globalLast;

    const int t    = threadIdx.x;
    const int tr   = t >> 4;     // 0..15 point group (8 pts each)
    const int tc   = t & 15;     // 0..15 code lane (codes j*16+tc)
    const int tile = blockIdx.x >> 2;
    const int ks   = blockIdx.x & 3;
    const int kc0  = ks * CHPS;
    const int n0   = tile * MT;
    const int b    = n0 >> 10;
    const int p0   = n0 & 1023;
    const float* xbase = inputs + (size_t)b * (CD * HW) + p0;

    const u32 es_base = smem_u32(sm + SM_ES0);
    const int skk = t >> 4;
    const int scg = (t & 15) << 2;

    // kick off async stage of first E chunk into buffer 0
    {
        const float* src = emb + (size_t)kc0 * KCH * CD + scg;
        #pragma unroll
        for (int j = 0; j < 4; ++j) {
            int kk = skk + j * 16;
            cp16(es_base + (u32)(kk * ESTRIDE + scg) * 4u, src + (size_t)kk * CD);
        }
    }
    cp_commit();

    // ---- load x tile (transposed into [c][p])
    #pragma unroll
    for (int j = 0; j < 8; ++j) {
        int q  = t + j * 256;
        int c  = q >> 5;
        int i4 = (q & 31) << 2;
        float4 v = *reinterpret_cast<const float4*>(xbase + (size_t)c * HW + i4);
        *reinterpret_cast<float4*>(&xs[c * XSTRIDE + i4]) = v;
    }
    __syncthreads();

    // a = ||x||^2 : strictly sequential fp32
    if (t < MT) {
        float s = 0.0f;
        #pragma unroll
        for (int c = 0; c < CD; ++c) {
            float xv = xs[c * XSTRIDE + t];
            s = __fadd_rn(s, __fmul_rn(xv, xv));
        }
        as_[t] = s;
    }
    __syncthreads();

    float bestv[8];
    int   besti[8];
    #pragma unroll
    for (int i = 0; i < 8; ++i) { bestv[i] = __int_as_float(0x7f800000); besti[i] = 0x7fffffff; }

    const u64 neg2 = pack_dup(-2.0f);

    #pragma unroll 1
    for (int kcl = 0; kcl < CHPS; ++kcl) {
        const int kc = kc0 + kcl;
        cp_wait0();
        __syncthreads();

        if (kcl + 1 < CHPS) {
            const float* src = emb + (size_t)(kc + 1) * KCH * CD + scg;
            u32 dstb = es_base + (u32)(((kcl + 1) & 1) * ESBUF + scg) * 4u;
            #pragma unroll
            for (int j = 0; j < 4; ++j) {
                int kk = skk + j * 16;
                cp16(dstb + (u32)(kk * ESTRIDE) * 4u, src + (size_t)kk * CD);
            }
        }
        cp_commit();

        const float* es = sm + SM_ES0 + (kcl & 1) * ESBUF;

        u64 acc[4][4];
        #pragma unroll
        for (int j = 0; j < 4; ++j)
            #pragma unroll
            for (int i = 0; i < 4; ++i) acc[j][i] = 0ULL;

        #pragma unroll 4
        for (int c4 = 0; c4 < CD; c4 += 4) {
            float4 ef[4];
            #pragma unroll
            for (int j = 0; j < 4; ++j)
                ef[j] = *reinterpret_cast<const float4*>(&es[(j * 16 + tc) * ESTRIDE + c4]);
            #pragma unroll
            for (int cc = 0; cc < 4; ++cc) {
                const float* xr = &xs[(c4 + cc) * XSTRIDE + tr * 8];
                ulonglong2 Xa = *reinterpret_cast<const ulonglong2*>(xr);
                ulonglong2 Xb = *reinterpret_cast<const ulonglong2*>(xr + 4);
                #pragma unroll
                for (int j = 0; j < 4; ++j) {
                    float ev = (cc == 0) ? ef[j].x : (cc == 1) ? ef[j].y : (cc == 2) ? ef[j].z : ef[j].w;
                    u64 ed = pack_dup(ev);
                    ffma2(acc[j][0], ed, Xa.x);
                    ffma2(acc[j][1], ed, Xa.y);
                    ffma2(acc[j][2], ed, Xb.x);
                    ffma2(acc[j][3], ed, Xb.y);
                }
            }
        }

        // ---- packed epilogue: dd2 = (a2 + (-2)*dot2) + esq2 (bit-identical)
        const u64* a2 = reinterpret_cast<const u64*>(&as_[tr * 8]);
        u64 A0 = a2[0], A1 = a2[1], A2 = a2[2], A3 = a2[3];
        #pragma unroll
        for (int j = 0; j < 4; ++j) {
            int k = kc * KCH + j * 16 + tc;
            u64 esq2 = pack_dup(__ldg(&g_esq[k]));
            #pragma unroll
            for (int i = 0; i < 4; ++i) {
                u64 Ai = (i == 0) ? A0 : (i == 1) ? A1 : (i == 2) ? A2 : A3;
                u64 dd2 = fadd2(ffma2_3(acc[j][i], neg2, Ai), esq2);
                float dd0, dd1; unpack2(dd2, dd0, dd1);
                int ii = i * 2;
                if (dd0 < bestv[ii])     { bestv[ii]     = dd0; besti[ii]     = k; }
                if (dd1 < bestv[ii + 1]) { bestv[ii + 1] = dd1; besti[ii + 1] = k; }
            }
        }
    }

    // cross-lane argmin over the 16 code lanes (first-index ties)
    #pragma unroll
    for (int off = 1; off < 16; off <<= 1) {
        #pragma unroll
        for (int i = 0; i < 8; ++i) {
            float ov = __shfl_xor_sync(0xffffffffu, bestv[i], off);
            int   oi = __shfl_xor_sync(0xffffffffu, besti[i], off);
            if (ov < bestv[i] || (ov == bestv[i] && oi < besti[i])) { bestv[i] = ov; besti[i] = oi; }
        }
    }
    // plain-store split winners: d>0 -> uint order == float order; u64 min
    // later prefers smaller k on ties (== first index).
    if (tc == 0) {
        u64* pb = g_part + ((size_t)tile * NSPLIT + ks) * MT + tr * 8;
        #pragma unroll
        for (int i = 0; i < 8; ++i)
            pb[i] = ((u64)__float_as_uint(bestv[i]) << 32) | (u32)besti[i];
        __threadfence();
    }
    __syncthreads();
    // replay-invariant ticket: each run adds exactly NSPLIT per tile
    if (t == 0) lastFlag = ((atomicAdd(&g_cnt[tile], 1) & (NSPLIT - 1)) == NSPLIT - 1);
    __syncthreads();
    if (!lastFlag) return;

    // ---- tile finalizer: reduce 4 partials -> idx/hist/quant/loss ----
    if (t < MT) {
        const u64* pb = g_part + (size_t)tile * NSPLIT * MT + t;
        u64 w = umin64(umin64(__ldcg(pb), __ldcg(pb + MT)),
                       umin64(__ldcg(pb + 2 * MT), __ldcg(pb + 3 * MT)));
        int k = (int)(w & 0xFFFFFFFFu);
        idxs[t] = k;
        out[OFF_IDX + n0 + t] = (float)k;
        atomicAdd(&g_hist[k], 1u);
    }
    __syncthreads();

    {
        const int p = t >> 1;
        const int h = t & 1;
        const int c0 = 32 * h;
        const int k = idxs[p];
        const float* eb = emb + (size_t)k * CD + c0;
        float* ob = out + (size_t)(n0 + p) * CD + c0;
        const float* xcol = xs + c0 * XSTRIDE + p;

        double s = 0.0;
        #pragma unroll
        for (int j = 0; j < 8; ++j) {
            float4 qv = __ldg(reinterpret_cast<const float4*>(eb) + j);
            float x0 = xcol[(4 * j + 0) * XSTRIDE];
            float x1 = xcol[(4 * j + 1) * XSTRIDE];
            float x2 = xcol[(4 * j + 2) * XSTRIDE];
            float x3 = xcol[(4 * j + 3) * XSTRIDE];
            float e0 = __fsub_rn(qv.x, x0);
            float e1 = __fsub_rn(qv.y, x1);
            float e2 = __fsub_rn(qv.z, x2);
            float e3 = __fsub_rn(qv.w, x3);
            float4 o;  // straight-through: x + (q - x)
            o.x = __fadd_rn(x0, e0);
            o.y = __fadd_rn(x1, e1);
            o.z = __fadd_rn(x2, e2);
            o.w = __fadd_rn(x3, e3);
            *reinterpret_cast<float4*>(ob + 4 * j) = o;
            s += (double)__fmul_rn(e0, e0) + (double)__fmul_rn(e1, e1)
               + (double)__fmul_rn(e2, e2) + (double)__fmul_rn(e3, e3);
        }
        #pragma unroll
        for (int off = 16; off > 0; off >>= 1)
            s += __shfl_down_sync(0xffffffffu, s, off);
        if ((t & 31) == 0) red[t >> 5] = s;
        __syncthreads();
        if (t == 0) {
            double tot = 0.0;
            #pragma unroll
            for (int w = 0; w < 8; ++w) tot += red[w];
            atomicAdd(&g_loss, tot);
        }
    }

    // ---- global last-finisher emits loss + perplexity ----
    __threadfence();
    __syncthreads();
    if (t == 0) globalLast = ((atomicAdd(&g_done, 1) & (NTILE - 1)) == NTILE - 1);
    __syncthreads();
    if (!globalLast) return;

    {
        double s = 0.0;
        for (int k = t; k < KC; k += 256) {
            float cnt = (float)__ldcg(&g_hist[k]);   // L2-coherent (post-fence)
            float pr  = __fmul_rn(cnt, 1.0f / 65536.0f);
            float lg  = logf(__fadd_rn(pr, 1e-10f));
            s += (double)__fmul_rn(pr, lg);
        }
        #pragma unroll
        for (int off = 16; off > 0; off >>= 1)
            s += __shfl_down_sync(0xffffffffu, s, off);
        if ((t & 31) == 0) red[32 + (t >> 5)] = s;
        __syncthreads();
        if (t == 0) {
            double S = 0.0;
            #pragma unroll
            for (int w = 0; w < 8; ++w) S += red[32 + w];
            double lossSum = atomicAdd(&g_loss, 0.0);   // coherent read
            float m = (float)(lossSum / 4194304.0);
            out[OFF_LOSS] = __fadd_rn(m, __fmul_rn(0.25f, m));
            out[OFF_PERP] = expf(-(float)S);
        }
    }
}

extern "C" void kernel_launch(void* const* d_in, const int* in_sizes, int n_in,
                              void* d_out, int out_size) {
    const float* inputs = (const float*)d_in[0];
    const float* emb    = (const float*)d_in[1];
    if (n_in >= 2 && in_sizes[0] == KC * CD && in_sizes[1] == NPTS * CD) {
        const float* tmp = inputs; inputs = emb; emb = tmp;
    }
    float* out = (float*)d_out;

    cudaFuncSetAttribute(vq_main, cudaFuncAttributeMaxDynamicSharedMemorySize, SMEM_BYTES);

    vq_pre<<<KC / 256, 256>>>(emb);
    vq_main<<<NTILE * NSPLIT, 256, SMEM_BYTES>>>(inputs, emb, out);
}

// round 16
// speedup vs baseline: 1.0111x; 1.0111x over previous
#include <cuda_runtime.h>
#include <math.h>

// VectorQuantizer: N=65536 (64x32x32 BHWC-flat), C=64, K=1024.
// Output (float32): [quantized 4194304][vq_loss 1][indices 65536][perplexity 1]
// Numerics verified bit-exact R1/R5/R7/R9/R10/R12/R13/R14.
// R16 = R14 mainloop (measured best, 92% of ffma2-rt3 roofline) with
// complemented-key winner merge: atomicMax of (~d_bits<<32)|(~k) makes ZERO the
// empty state -> no g_win init kernel; finalizer atomicExch(ptr,0) self-resets
// for graph replay. Tie semantics identical (max ~k == min k == first index).

#define NPTS   65536
#define KC     1024
#define CD     64
#define HW     1024
#define MT     128
#define KCH    64
#define NSPLIT 4
#define CHPS   4              // chunks per split (4*64 = 256 codes)
#define NTILE  (NPTS / MT)    // 512
#define XSTRIDE 132
#define ESTRIDE 68
#define ESBUF   (KCH * ESTRIDE)

#define SM_XS   0
#define SM_ES0  (CD * XSTRIDE)           // 8448
#define SM_AS   (SM_ES0 + 2 * ESBUF)     // 17152
#define SM_IDX  (SM_AS + 128)
#define SMEM_FLOATS (SM_IDX + 128)       // 69,632 B -> 2 blocks/SM
#define SMEM_BYTES  (SMEM_FLOATS * 4)

#define OFF_LOSS  4194304
#define OFF_IDX   4194305
#define OFF_PERP  4259841

typedef unsigned long long u64;
typedef unsigned int u32;

__device__ float        g_esq[KC];
__device__ unsigned int g_hist[KC];
__device__ double       g_loss;
__device__ u64          g_win[NPTS];     // complemented keys; 0 == empty (replay-safe)
__device__ int          g_cnt[NTILE];    // mod-NSPLIT tickets (never re-init)
__device__ int          g_done;          // mod-NTILE ticket (never re-init)

__device__ __forceinline__ u64 pack_dup(float x) {
    u64 r; asm("mov.b64 %0, {%1, %1};" : "=l"(r) : "f"(x)); return r;
}
__device__ __forceinline__ void unpack2(u64 v, float &lo, float &hi) {
    asm("mov.b64 {%0, %1}, %2;" : "=f"(lo), "=f"(hi) : "l"(v));
}
// packed fp32x2 FMA: each lane is IEEE-rn fp32 FMA (bit-identical to scalar FFMA)
__device__ __forceinline__ void ffma2(u64 &acc, u64 a, u64 b) {
    asm("fma.rn.f32x2 %0, %1, %2, %0;" : "+l"(acc) : "l"(a), "l"(b));
}
__device__ __forceinline__ u64 ffma2_3(u64 a, u64 b, u64 c) {
    u64 r; asm("fma.rn.f32x2 %0, %1, %2, %3;" : "=l"(r) : "l"(a), "l"(b), "l"(c)); return r;
}
__device__ __forceinline__ u64 fadd2(u64 a, u64 b) {
    u64 r; asm("add.rn.f32x2 %0, %1, %2;" : "=l"(r) : "l"(a), "l"(b)); return r;
}
__device__ __forceinline__ u32 smem_u32(const void* p) {
    u32 a; asm("{ .reg .u64 t; cvta.to.shared.u64 t, %1; cvt.u32.u64 %0, t; }" : "=r"(a) : "l"(p));
    return a;
}
__device__ __forceinline__ void cp16(u32 dst, const void* src) {
    asm volatile("cp.async.cg.shared.global [%0], [%1], 16;" :: "r"(dst), "l"(src));
}
__device__ __forceinline__ void cp_commit() {
    asm volatile("cp.async.commit_group;" ::: "memory");
}
__device__ __forceinline__ void cp_wait0() {
    asm volatile("cp.async.wait_group 0;" ::: "memory");
}

// ---------------- pre: esq + hist/loss init (1024 threads) ----------------
__global__ void vq_pre(const float* __restrict__ emb) {
    int tid = blockIdx.x * blockDim.x + threadIdx.x;   // 0..1023
    float s = 0.0f;
    const float* er = emb + (size_t)tid * CD;
    #pragma unroll
    for (int c = 0; c < CD; ++c) {
        float e = er[c];
        s = __fadd_rn(s, __fmul_rn(e, e));
    }
    g_esq[tid] = s;
    g_hist[tid] = 0u;
    if (tid == 0) g_loss = 0.0;
}

// ------- job = (tile, ksplit): distances + argmin-merge; last split per tile
//         finalizes; globally-last finisher emits loss + perplexity -------
__global__ void __launch_bounds__(256, 2) vq_main(const float* __restrict__ inputs,
                                                  const float* __restrict__ emb,
                                                  float* __restrict__ out) {
    extern __shared__ float sm[];
    float* xs   = sm + SM_XS;    // [CD][XSTRIDE]  xs[c*XSTRIDE + p]
    float* as_  = sm + SM_AS;    // [128] ||x||^2 (point-pair aligned)
    int*   idxs = (int*)(sm + SM_IDX);
    double* red = (double*)(sm + SM_ES0);  // tail scratch (es dead then)
    __shared__ int lastFlag;
    __shared__ int globalLast;

    const int t    = threadIdx.x;
    const int tr   = t >> 4;     // 0..15 point group (8 pts each)
    const int tc   = t & 15;     // 0..15 code lane (codes j*16+tc)
    const int tile = blockIdx.x >> 2;
    const int ks   = blockIdx.x & 3;
    const int kc0  = ks * CHPS;
    const int n0   = tile * MT;
    const int b    = n0 >> 10;
    const int p0   = n0 & 1023;
    const float* xbase = inputs + (size_t)b * (CD * HW) + p0;

    const u32 es_base = smem_u32(sm + SM_ES0);
    const int skk = t >> 4;
    const int scg = (t & 15) << 2;

    // kick off async stage of first E chunk into buffer 0
    {
        const float* src = emb + (size_t)kc0 * KCH * CD + scg;
        #pragma unroll
        for (int j = 0; j < 4; ++j) {
            int kk = skk + j * 16;
            cp16(es_base + (u32)(kk * ESTRIDE + scg) * 4u, src + (size_t)kk * CD);
        }
    }
    cp_commit();

    // ---- load x tile (transposed into [c][p])
    #pragma unroll
    for (int j = 0; j < 8; ++j) {
        int q  = t + j * 256;
        int c  = q >> 5;
        int i4 = (q & 31) << 2;
        float4 v = *reinterpret_cast<const float4*>(xbase + (size_t)c * HW + i4);
        *reinterpret_cast<float4*>(&xs[c * XSTRIDE + i4]) = v;
    }
    __syncthreads();

    // a = ||x||^2 : strictly sequential fp32
    if (t < MT) {
        float s = 0.0f;
        #pragma unroll
        for (int c = 0; c < CD; ++c) {
            float xv = xs[c * XSTRIDE + t];
            s = __fadd_rn(s, __fmul_rn(xv, xv));
        }
        as_[t] = s;
    }
    __syncthreads();

    float bestv[8];
    int   besti[8];
    #pragma unroll
    for (int i = 0; i < 8; ++i) { bestv[i] = __int_as_float(0x7f800000); besti[i] = 0x7fffffff; }

    const u64 neg2 = pack_dup(-2.0f);

    #pragma unroll 1
    for (int kcl = 0; kcl < CHPS; ++kcl) {
        const int kc = kc0 + kcl;
        cp_wait0();
        __syncthreads();

        if (kcl + 1 < CHPS) {
            const float* src = emb + (size_t)(kc + 1) * KCH * CD + scg;
            u32 dstb = es_base + (u32)(((kcl + 1) & 1) * ESBUF + scg) * 4u;
            #pragma unroll
            for (int j = 0; j < 4; ++j) {
                int kk = skk + j * 16;
                cp16(dstb + (u32)(kk * ESTRIDE) * 4u, src + (size_t)kk * CD);
            }
        }
        cp_commit();

        const float* es = sm + SM_ES0 + (kcl & 1) * ESBUF;

        u64 acc[4][4];
        #pragma unroll
        for (int j = 0; j < 4; ++j)
            #pragma unroll
            for (int i = 0; i < 4; ++i) acc[j][i] = 0ULL;

        #pragma unroll 4
        for (int c4 = 0; c4 < CD; c4 += 4) {
            float4 ef[4];
            #pragma unroll
            for (int j = 0; j < 4; ++j)
                ef[j] = *reinterpret_cast<const float4*>(&es[(j * 16 + tc) * ESTRIDE + c4]);
            #pragma unroll
            for (int cc = 0; cc < 4; ++cc) {
                const float* xr = &xs[(c4 + cc) * XSTRIDE + tr * 8];
                ulonglong2 Xa = *reinterpret_cast<const ulonglong2*>(xr);
                ulonglong2 Xb = *reinterpret_cast<const ulonglong2*>(xr + 4);
                #pragma unroll
                for (int j = 0; j < 4; ++j) {
                    float ev = (cc == 0) ? ef[j].x : (cc == 1) ? ef[j].y : (cc == 2) ? ef[j].z : ef[j].w;
                    u64 ed = pack_dup(ev);
                    ffma2(acc[j][0], ed, Xa.x);
                    ffma2(acc[j][1], ed, Xa.y);
                    ffma2(acc[j][2], ed, Xb.x);
                    ffma2(acc[j][3], ed, Xb.y);
                }
            }
        }

        // ---- packed epilogue: dd2 = (a2 + (-2)*dot2) + esq2 (bit-identical)
        const u64* a2 = reinterpret_cast<const u64*>(&as_[tr * 8]);
        u64 A0 = a2[0], A1 = a2[1], A2 = a2[2], A3 = a2[3];
        #pragma unroll
        for (int j = 0; j < 4; ++j) {
            int k = kc * KCH + j * 16 + tc;
            u64 esq2 = pack_dup(__ldg(&g_esq[k]));
            #pragma unroll
            for (int i = 0; i < 4; ++i) {
                u64 Ai = (i == 0) ? A0 : (i == 1) ? A1 : (i == 2) ? A2 : A3;
                u64 dd2 = fadd2(ffma2_3(acc[j][i], neg2, Ai), esq2);
                float dd0, dd1; unpack2(dd2, dd0, dd1);
                int ii = i * 2;
                if (dd0 < bestv[ii])     { bestv[ii]     = dd0; besti[ii]     = k; }
                if (dd1 < bestv[ii + 1]) { bestv[ii + 1] = dd1; besti[ii + 1] = k; }
            }
        }
    }

    // cross-lane argmin over the 16 code lanes (first-index ties)
    #pragma unroll
    for (int off = 1; off < 16; off <<= 1) {
        #pragma unroll
        for (int i = 0; i < 8; ++i) {
            float ov = __shfl_xor_sync(0xffffffffu, bestv[i], off);
            int   oi = __shfl_xor_sync(0xffffffffu, besti[i], off);
            if (ov < bestv[i] || (ov == bestv[i] && oi < besti[i])) { bestv[i] = ov; besti[i] = oi; }
        }
    }
    // merge split winners: complemented key, atomicMax. d>0 -> uint order ==
    // float order, so max(~d_bits) == min(d); on d-ties max(~k) == min(k)
    // (first index). Zero == empty, so no init kernel is needed.
    if (tc == 0) {
        #pragma unroll
        for (int i = 0; i < 8; ++i) {
            int n = n0 + tr * 8 + i;
            u64 pk = ((u64)(~__float_as_uint(bestv[i])) << 32) | (u32)(~besti[i]);
            atomicMax(&g_win[n], pk);
        }
        __threadfence();
    }
    __syncthreads();
    // replay-invariant ticket: each run adds exactly NSPLIT per tile
    if (t == 0) lastFlag = ((atomicAdd(&g_cnt[tile], 1) & (NSPLIT - 1)) == NSPLIT - 1);
    __syncthreads();
    if (!lastFlag) return;

    // ---- tile finalizer: read winners (and reset to 0 for the next replay) ----
    if (t < MT) {
        u64 w = atomicExch(&g_win[n0 + t], 0ULL);   // coherent read + self-reset
        int k = (int)(~(u32)(w & 0xFFFFFFFFu));
        idxs[t] = k;
        out[OFF_IDX + n0 + t] = (float)k;
        atomicAdd(&g_hist[k], 1u);
    }
    __syncthreads();

    {
        const int p = t >> 1;
        const int h = t & 1;
        const int c0 = 32 * h;
        const int k = idxs[p];
        const float* eb = emb + (size_t)k * CD + c0;
        float* ob = out + (size_t)(n0 + p) * CD + c0;
        const float* xcol = xs + c0 * XSTRIDE + p;

        double s = 0.0;
        #pragma unroll
        for (int j = 0; j < 8; ++j) {
            float4 qv = __ldg(reinterpret_cast<const float4*>(eb) + j);
            float x0 = xcol[(4 * j + 0) * XSTRIDE];
            float x1 = xcol[(4 * j + 1) * XSTRIDE];
            float x2 = xcol[(4 * j + 2) * XSTRIDE];
            float x3 = xcol[(4 * j + 3) * XSTRIDE];
            float e0 = __fsub_rn(qv.x, x0);
            float e1 = __fsub_rn(qv.y, x1);
            float e2 = __fsub_rn(qv.z, x2);
            float e3 = __fsub_rn(qv.w, x3);
            float4 o;  // straight-through: x + (q - x)
            o.x = __fadd_rn(x0, e0);
            o.y = __fadd_rn(x1, e1);
            o.z = __fadd_rn(x2, e2);
            o.w = __fadd_rn(x3, e3);
            *reinterpret_cast<float4*>(ob + 4 * j) = o;
            s += (double)__fmul_rn(e0, e0) + (double)__fmul_rn(e1, e1)
               + (double)__fmul_rn(e2, e2) + (double)__fmul_rn(e3, e3);
        }
        #pragma unroll
        for (int off = 16; off > 0; off >>= 1)
            s += __shfl_down_sync(0xffffffffu, s, off);
        if ((t & 31) == 0) red[t >> 5] = s;
        __syncthreads();
        if (t == 0) {
            double tot = 0.0;
            #pragma unroll
            for (int w = 0; w < 8; ++w) tot += red[w];
            atomicAdd(&g_loss, tot);
        }
    }

    // ---- global last-finisher emits loss + perplexity ----
    __threadfence();
    __syncthreads();
    if (t == 0) globalLast = ((atomicAdd(&g_done, 1) & (NTILE - 1)) == NTILE - 1);
    __syncthreads();
    if (!globalLast) return;

    {
        double s = 0.0;
        for (int k = t; k < KC; k += 256) {
            float cnt = (float)__ldcg(&g_hist[k]);   // L2-coherent (post-fence)
            float pr  = __fmul_rn(cnt, 1.0f / 65536.0f);
            float lg  = logf(__fadd_rn(pr, 1e-10f));
            s += (double)__fmul_rn(pr, lg);
        }
        #pragma unroll
        for (int off = 16; off > 0; off >>= 1)
            s += __shfl_down_sync(0xffffffffu, s, off);
        if ((t & 31) == 0) red[32 + (t >> 5)] = s;
        __syncthreads();
        if (t == 0) {
            double S = 0.0;
            #pragma unroll
            for (int w = 0; w < 8; ++w) S += red[32 + w];
            double lossSum = atomicAdd(&g_loss, 0.0);   // coherent read
            float m = (float)(lossSum / 4194304.0);
            out[OFF_LOSS] = __fadd_rn(m, __fmul_rn(0.25f, m));
            out[OFF_PERP] = expf(-(float)S);
        }
    }
}

extern "C" void kernel_launch(void* const* d_in, const int* in_sizes, int n_in,
                              void* d_out, int out_size) {
    const float* inputs = (const float*)d_in[0];
    const float* emb    = (const float*)d_in[1];
    if (n_in >= 2 && in_sizes[0] == KC * CD && in_sizes[1] == NPTS * CD) {
        const float* tmp = inputs; inputs = emb; emb = tmp;
    }
    float* out = (float*)d_out;

    cudaFuncSetAttribute(vq_main, cudaFuncAttributeMaxDynamicSharedMemorySize, SMEM_BYTES);

    vq_pre<<<KC / 256, 256>>>(emb);
    vq_main<<<NTILE * NSPLIT, 256, SMEM_BYTES>>>(inputs, emb, out);
}